// round 1
// baseline (speedup 1.0000x reference)
#include <cuda_runtime.h>
#include <cuda_bf16.h>

// ---------------------------------------------------------------------------
// Problem constants
// ---------------------------------------------------------------------------
constexpr int H    = 4;
constexpr int C    = 16;
constexpr int DIN  = 128;
constexpr int DOUT = 64;
constexpr int NA   = 150000;
constexpr int NP   = 200000;
constexpr int NOUT = 50000;
constexpr int E    = 1000000;

// ---------------------------------------------------------------------------
// Device scratch (static; no allocations allowed)
// ---------------------------------------------------------------------------
__device__ __align__(16) float g_l_author[(size_t)NA * DOUT];   // 38.4 MB
__device__ __align__(16) float g_l_paper [(size_t)NP * DOUT];   // 51.2 MB
__device__ __align__(16) float g_asrc_w  [(size_t)NA * H];      // per-source logit term (writes)
__device__ __align__(16) float g_asrc_c  [(size_t)NP * H];      // per-source logit term (cites)
__device__ int   g_cnt [2][NOUT];
__device__ int   g_off [2][NOUT + 1];
__device__ int   g_cur [2][NOUT];
__device__ int   g_csrc[2][E];
__device__ __align__(16) float g_ca  [2][(size_t)E * H];        // per-edge logits, CSR order
__device__ __align__(16) float g_emb [2][(size_t)NOUT * DOUT];

// ---------------------------------------------------------------------------
// K1: fused GEMM  l = x @ W + b   (N x 128) @ (128 x 64)
//     epilogue also computes alpha_src[n,h] = sum_c lrelu(l[n,h,c]) * attn[h, C+c]
//     mode 0 -> l_author / asrc_w (attn_writes), mode 1 -> l_paper / asrc_c (attn_cites)
//     Uses packed fp32x2 FMA (Blackwell) for 2x FFMA throughput; exact fp32 math.
// ---------------------------------------------------------------------------
__global__ __launch_bounds__(256, 2) void k_gemm(
    const float* __restrict__ A, int N,
    const float* __restrict__ W, const float* __restrict__ bias,
    const float* __restrict__ attn, int mode)
{
    __shared__ __align__(16) float Ws[DIN * DOUT];   // 32 KB: whole weight matrix
    __shared__ __align__(16) float As[16 * 130];     // 8.3 KB: 16-k x 128-row slab (transposed, padded)

    float* out = (mode == 0) ? g_l_author : g_l_paper;
    float* alA = (mode == 0) ? g_asrc_w   : g_asrc_c;

    const int tid = threadIdx.x;
    const int tx  = tid & 15;        // 16 col-groups of 4 cols
    const int ty  = tid >> 4;        // 16 row-groups of 8 rows

    // load full W into shared (row-major [k][64])
    {
        const float4* W4  = (const float4*)W;
        float4*       Ws4 = (float4*)Ws;
        #pragma unroll
        for (int i = 0; i < (DIN * DOUT / 4) / 256; i++)
            Ws4[tid + i * 256] = W4[tid + i * 256];
    }

    unsigned long long acc[4][4];    // 4 row-pairs (f32x2 over rows) x 4 cols
    #pragma unroll
    for (int i = 0; i < 4; i++) {
        #pragma unroll
        for (int j = 0; j < 4; j++) acc[i][j] = 0ull;
    }

    const int row0 = blockIdx.x * 128;
    const int lrow = tid >> 1;              // row this thread loads
    const int lk   = (tid & 1) * 8;         // k-offset within 16-k slab
    const int grld = row0 + lrow;
    const bool vld = grld < N;
    const float* Arow = A + (size_t)grld * DIN + lk;

    for (int kc = 0; kc < DIN; kc += 16) {
        __syncthreads();
        float4 v0, v1;
        if (vld) {
            v0 = *(const float4*)(Arow + kc);
            v1 = *(const float4*)(Arow + kc + 4);
        } else {
            v0 = make_float4(0.f, 0.f, 0.f, 0.f); v1 = v0;
        }
        As[(lk + 0) * 130 + lrow] = v0.x;
        As[(lk + 1) * 130 + lrow] = v0.y;
        As[(lk + 2) * 130 + lrow] = v0.z;
        As[(lk + 3) * 130 + lrow] = v0.w;
        As[(lk + 4) * 130 + lrow] = v1.x;
        As[(lk + 5) * 130 + lrow] = v1.y;
        As[(lk + 6) * 130 + lrow] = v1.z;
        As[(lk + 7) * 130 + lrow] = v1.w;
        __syncthreads();

        #pragma unroll
        for (int k = 0; k < 16; k++) {
            unsigned long long a[4];
            #pragma unroll
            for (int rp = 0; rp < 4; rp++)
                a[rp] = *(const unsigned long long*)&As[k * 130 + ty * 8 + rp * 2];
            float4 wv = *(const float4*)&Ws[(kc + k) * DOUT + tx * 4];
            unsigned long long wd[4];
            unsigned wb;
            wb = __float_as_uint(wv.x); asm("mov.b64 %0,{%1,%1};" : "=l"(wd[0]) : "r"(wb));
            wb = __float_as_uint(wv.y); asm("mov.b64 %0,{%1,%1};" : "=l"(wd[1]) : "r"(wb));
            wb = __float_as_uint(wv.z); asm("mov.b64 %0,{%1,%1};" : "=l"(wd[2]) : "r"(wb));
            wb = __float_as_uint(wv.w); asm("mov.b64 %0,{%1,%1};" : "=l"(wd[3]) : "r"(wb));
            #pragma unroll
            for (int rp = 0; rp < 4; rp++) {
                #pragma unroll
                for (int c = 0; c < 4; c++)
                    asm("fma.rn.f32x2 %0, %1, %2, %0;"
                        : "+l"(acc[rp][c]) : "l"(a[rp]), "l"(wd[c]));
            }
        }
    }

    // unpack accumulators -> vals[8 rows][4 cols]
    float vals[8][4];
    #pragma unroll
    for (int rp = 0; rp < 4; rp++) {
        #pragma unroll
        for (int c = 0; c < 4; c++) {
            unsigned lo, hi;
            asm("mov.b64 {%0,%1}, %2;" : "=r"(lo), "=r"(hi) : "l"(acc[rp][c]));
            vals[rp * 2    ][c] = __uint_as_float(lo);
            vals[rp * 2 + 1][c] = __uint_as_float(hi);
        }
    }
    float bj[4];
    #pragma unroll
    for (int j = 0; j < 4; j++) bj[j] = __ldg(&bias[tx * 4 + j]);
    #pragma unroll
    for (int r = 0; r < 8; r++) {
        #pragma unroll
        for (int j = 0; j < 4; j++) vals[r][j] += bj[j];
    }

    // store l (coalesced float4 per row)
    #pragma unroll
    for (int r = 0; r < 8; r++) {
        int gr = row0 + ty * 8 + r;
        if (gr < N)
            *(float4*)&out[(size_t)gr * DOUT + tx * 4] =
                make_float4(vals[r][0], vals[r][1], vals[r][2], vals[r][3]);
    }

    // fused alpha_src: head = tx/4, channels (tx&3)*4 .. +3 within head; uses attn[h, C + c]
    const int h  = tx >> 2;
    const int cb = (tx & 3) * 4;
    float aw[4];
    #pragma unroll
    for (int j = 0; j < 4; j++) aw[j] = __ldg(&attn[h * (2 * C) + C + cb + j]);
    #pragma unroll
    for (int r = 0; r < 8; r++) {
        float p = 0.f;
        #pragma unroll
        for (int j = 0; j < 4; j++) {
            float v = vals[r][j];
            p += fmaxf(v, 0.2f * v) * aw[j];   // leaky_relu(v) = max(v, 0.2v)
        }
        p += __shfl_xor_sync(0xffffffffu, p, 1);
        p += __shfl_xor_sync(0xffffffffu, p, 2);
        if ((tx & 3) == 0) {
            int gr = row0 + ty * 8 + r;
            if (gr < N) alA[(size_t)gr * H + h] = p;
        }
    }
}

// ---------------------------------------------------------------------------
// K0: zero edge counters
// ---------------------------------------------------------------------------
__global__ void k_zero() {
    int i = blockIdx.x * 256 + threadIdx.x;
    if (i < 2 * NOUT) (&g_cnt[0][0])[i] = 0;
}

// ---------------------------------------------------------------------------
// K2: histogram of destinations
// ---------------------------------------------------------------------------
__global__ void k_hist(const int* __restrict__ dst, int rel) {
    int i = blockIdx.x * 256 + threadIdx.x;
    if (i < E) atomicAdd(&g_cnt[rel][dst[i]], 1);
}

// ---------------------------------------------------------------------------
// K3: single-block exclusive scan over 50000 counts -> offsets + cursors
// ---------------------------------------------------------------------------
__global__ void k_scan(int rel) {
    __shared__ int sh[1024];
    const int CH = (NOUT + 1023) / 1024;   // 49
    int t  = threadIdx.x;
    int s0 = t * CH;
    int s1 = s0 + CH; if (s1 > NOUT) s1 = NOUT;
    int sum = 0;
    for (int i = s0; i < s1; i++) sum += g_cnt[rel][i];
    sh[t] = sum;
    __syncthreads();
    for (int o = 1; o < 1024; o <<= 1) {
        int v = (t >= o) ? sh[t - o] : 0;
        __syncthreads();
        sh[t] += v;
        __syncthreads();
    }
    int base = sh[t] - sum;                // exclusive prefix
    for (int i = s0; i < s1; i++) {
        g_off[rel][i] = base;
        g_cur[rel][i] = base;
        base += g_cnt[rel][i];
    }
    if (s0 < NOUT && s1 == NOUT) g_off[rel][NOUT] = base;
}

// ---------------------------------------------------------------------------
// K4: scatter edges into CSR; precompute per-edge logits (gather alpha_src once)
// ---------------------------------------------------------------------------
__global__ void k_scatter(const int* __restrict__ src, const int* __restrict__ dst, int rel) {
    int i = blockIdx.x * 256 + threadIdx.x;
    if (i >= E) return;
    int d = dst[i], s = src[i];
    const float* asrc = (rel == 0) ? g_asrc_w : g_asrc_c;
    int pos = atomicAdd(&g_cur[rel][d], 1);
    g_csrc[rel][pos] = s;
    float4 av = *(const float4*)&asrc[(size_t)s * H];
    *(float4*)&g_ca[rel][(size_t)pos * H] = av;
}

// ---------------------------------------------------------------------------
// K5: per-destination softmax aggregation. One warp per destination node.
//     Note: the x_i logit term is constant per segment -> softmax-invariant,
//     so only the per-edge alpha_src terms matter (the whole W_r_paper path
//     of the reference is mathematically dead).
// ---------------------------------------------------------------------------
__global__ __launch_bounds__(256) void k_agg(int rel) {
    const float* __restrict__ lsrc = (rel == 0) ? g_l_author : g_l_paper;
    const int*   off  = g_off[rel];
    const int*   csrc = g_csrc[rel];
    const float* ca   = g_ca[rel];
    float*       emb  = g_emb[rel];

    int w = blockIdx.x * 8 + (threadIdx.x >> 5);
    if (w >= NOUT) return;
    int lane = threadIdx.x & 31;
    int h    = lane >> 3;                 // 8 lanes (16 channels) per head

    int beg = off[w], end = off[w + 1];
    float m = -1e30f;
    for (int e = beg; e < end; e++)
        m = fmaxf(m, ca[(size_t)e * H + h]);

    float s = 0.f, a0 = 0.f, a1 = 0.f;
    for (int e = beg; e < end; e++) {
        float wg = __expf(ca[(size_t)e * H + h] - m);
        s += wg;
        int srci = csrc[e];
        float2 xj = *(const float2*)&lsrc[(size_t)srci * DOUT + lane * 2];
        a0 += wg * xj.x;
        a1 += wg * xj.y;
    }
    float inv = 1.f / (s + 1e-16f);
    *(float2*)&emb[(size_t)w * DOUT + lane * 2] = make_float2(a0 * inv, a1 * inv);
}

// ---------------------------------------------------------------------------
// K6: semantic attention over {writes, cites, self} + relu. Warp per node.
// ---------------------------------------------------------------------------
__global__ __launch_bounds__(256) void k_final(
    const float* __restrict__ rel_l, const float* __restrict__ rel_r,
    float* __restrict__ outp)
{
    int n = blockIdx.x * 8 + (threadIdx.x >> 5);
    if (n >= NOUT) return;
    int lane = threadIdx.x & 31;
    int h  = lane >> 3;
    int c0 = lane * 2;
    int ci = c0 & 15;

    float2 ew = *(const float2*)&g_emb[0][(size_t)n * DOUT + c0];
    float2 ec = *(const float2*)&g_emb[1][(size_t)n * DOUT + c0];
    float2 es = *(const float2*)&g_l_paper[(size_t)n * DOUT + c0];

    float al = es.x * __ldg(&rel_l[h * C + ci]) + es.y * __ldg(&rel_l[h * C + ci + 1]);
    float r0 = ew.x * __ldg(&rel_r[0 * H * C + h * C + ci]) + ew.y * __ldg(&rel_r[0 * H * C + h * C + ci + 1]);
    float r1 = ec.x * __ldg(&rel_r[1 * H * C + h * C + ci]) + ec.y * __ldg(&rel_r[1 * H * C + h * C + ci + 1]);
    float r2 = es.x * __ldg(&rel_r[2 * H * C + h * C + ci]) + es.y * __ldg(&rel_r[2 * H * C + h * C + ci + 1]);

    #pragma unroll
    for (int o = 1; o <= 4; o <<= 1) {
        al += __shfl_xor_sync(0xffffffffu, al, o);
        r0 += __shfl_xor_sync(0xffffffffu, r0, o);
        r1 += __shfl_xor_sync(0xffffffffu, r1, o);
        r2 += __shfl_xor_sync(0xffffffffu, r2, o);
    }

    float x0 = al + r0; x0 = fmaxf(x0, 0.2f * x0);
    float x1 = al + r1; x1 = fmaxf(x1, 0.2f * x1);
    float x2 = al + r2; x2 = fmaxf(x2, 0.2f * x2);
    float mx = fmaxf(x0, fmaxf(x1, x2));
    float e0 = __expf(x0 - mx), e1 = __expf(x1 - mx), e2 = __expf(x2 - mx);
    float ib = 1.f / (e0 + e1 + e2);
    float b0 = e0 * ib, b1 = e1 * ib, b2 = e2 * ib;

    float o0 = fmaxf(ew.x * b0 + ec.x * b1 + es.x * b2, 0.f);
    float o1 = fmaxf(ew.y * b0 + ec.y * b1 + es.y * b2, 0.f);
    *(float2*)&outp[(size_t)n * DOUT + c0] = make_float2(o0, o1);
}

// ---------------------------------------------------------------------------
// Launch
// ---------------------------------------------------------------------------
extern "C" void kernel_launch(void* const* d_in, const int* in_sizes, int n_in,
                              void* d_out, int out_size) {
    (void)in_sizes; (void)n_in; (void)out_size;
    const float* x_author   = (const float*)d_in[0];
    const float* x_paper    = (const float*)d_in[1];
    const float* W_l_author = (const float*)d_in[2];
    const float* b_l_author = (const float*)d_in[3];
    const float* W_l_paper  = (const float*)d_in[4];
    const float* b_l_paper  = (const float*)d_in[5];
    // d_in[6], d_in[7] (W_r_paper, b_r_paper): softmax-invariant -> unused
    const float* attn_w     = (const float*)d_in[8];
    const float* attn_c     = (const float*)d_in[9];
    const float* rel_l      = (const float*)d_in[10];
    const float* rel_r      = (const float*)d_in[11];
    const int*   src_w      = (const int*)d_in[12];
    const int*   dst_w      = (const int*)d_in[13];
    const int*   src_c      = (const int*)d_in[14];
    const int*   dst_c      = (const int*)d_in[15];
    float* outp = (float*)d_out;

    k_zero<<<(2 * NOUT + 255) / 256, 256>>>();
    k_gemm<<<(NA + 127) / 128, 256>>>(x_author, NA, W_l_author, b_l_author, attn_w, 0);
    k_gemm<<<(NP + 127) / 128, 256>>>(x_paper,  NP, W_l_paper,  b_l_paper,  attn_c, 1);
    k_hist<<<(E + 255) / 256, 256>>>(dst_w, 0);
    k_hist<<<(E + 255) / 256, 256>>>(dst_c, 1);
    k_scan<<<1, 1024>>>(0);
    k_scan<<<1, 1024>>>(1);
    k_scatter<<<(E + 255) / 256, 256>>>(src_w, dst_w, 0);
    k_scatter<<<(E + 255) / 256, 256>>>(src_c, dst_c, 1);
    k_agg<<<(NOUT + 7) / 8, 256>>>(0);
    k_agg<<<(NOUT + 7) / 8, 256>>>(1);
    k_final<<<(NOUT + 7) / 8, 256>>>(rel_l, rel_r, outp);
}

// round 6
// speedup vs baseline: 1.4400x; 1.4400x over previous
#include <cuda_runtime.h>
#include <cuda_bf16.h>
#include <cstdint>

// ---------------------------------------------------------------------------
// Problem constants
// ---------------------------------------------------------------------------
constexpr int H    = 4;
constexpr int C    = 16;
constexpr int DIN  = 128;
constexpr int DOUT = 64;
constexpr int NA   = 150000;
constexpr int NP   = 200000;
constexpr int NOUT = 50000;
constexpr int E    = 1000000;

// ---------------------------------------------------------------------------
// Device scratch (static; no allocations allowed)
// ---------------------------------------------------------------------------
__device__ __align__(16) float g_l_author[(size_t)NA * DOUT];   // 38.4 MB
__device__ __align__(16) float g_l_paper [(size_t)NP * DOUT];   // 51.2 MB
__device__ __align__(16) float g_asrc_w  [(size_t)NA * H];      // per-source logit term
__device__ __align__(16) float g_asrc_c  [(size_t)NP * H];
__device__ int g_cnt [2][NOUT];
__device__ int g_off [2][NOUT + 1];
__device__ int g_cur [2][NOUT];
__device__ int g_csrc[2][E];
__device__ __align__(16) float g_emb[2][(size_t)NOUT * DOUT];

// fp32 -> (bf16 hi, bf16 lo residual) packed pairs
__device__ __forceinline__ void split2(float a, float b, uint32_t& hi, uint32_t& lo) {
    __nv_bfloat162 h = __floats2bfloat162_rn(a, b);
    float2 hf = __bfloat1622float2(h);
    __nv_bfloat162 l = __floats2bfloat162_rn(a - hf.x, b - hf.y);
    hi = *(uint32_t*)&h;
    lo = *(uint32_t*)&l;
}

__device__ __forceinline__ void mma16816(float* c, uint32_t a0, uint32_t a1, uint32_t a2,
                                         uint32_t a3, uint32_t b0, uint32_t b1) {
    asm volatile(
        "mma.sync.aligned.m16n8k16.row.col.f32.bf16.bf16.f32 "
        "{%0,%1,%2,%3}, {%4,%5,%6,%7}, {%8,%9}, {%0,%1,%2,%3};"
        : "+f"(c[0]), "+f"(c[1]), "+f"(c[2]), "+f"(c[3])
        : "r"(a0), "r"(a1), "r"(a2), "r"(a3), "r"(b0), "r"(b1));
}

// ---------------------------------------------------------------------------
// K1: bf16-split mma.sync GEMM  l = x @ W + b  (tile 128 rows x 64 cols / CTA)
//     3 passes: A_hi*W_hi + A_hi*W_lo + A_lo*W_hi  -> fp32 acc (err ~2^-16)
//     Fused epilogue: bias, store l, alpha_src[n,h] = sum_c lrelu(l)*attn[h,C+c]
// ---------------------------------------------------------------------------
constexpr int KCH   = 32;            // k-chunk
constexpr int APAD  = 40;            // row stride in halfs (32 + 8 pad) -> conflict-free
constexpr int S_AH  = 0;             // 128*40*2 = 10240
constexpr int S_AL  = 10240;
constexpr int S_WH  = 20480;         // 64*40*2 = 5120
constexpr int S_WL  = 25600;
constexpr int S_OS  = 0;             // output staging 128 x 66 fp32 = 33792 (reuses A/W)
constexpr int S_BS  = 33792;         // 64 floats bias
constexpr int S_AT  = 34048;         // 64 floats attn (col-indexed)
constexpr int GSMEM = 34304;

__global__ __launch_bounds__(256, 3) void k_gemm_mma(
    const float* __restrict__ A, int N,
    const float* __restrict__ W, const float* __restrict__ bias,
    const float* __restrict__ attn, int mode)
{
    __shared__ __align__(16) char smem[GSMEM];
    __nv_bfloat16* Ah = (__nv_bfloat16*)(smem + S_AH);
    __nv_bfloat16* Al = (__nv_bfloat16*)(smem + S_AL);
    __nv_bfloat16* Wh = (__nv_bfloat16*)(smem + S_WH);
    __nv_bfloat16* Wl = (__nv_bfloat16*)(smem + S_WL);
    float* bs  = (float*)(smem + S_BS);
    float* as_ = (float*)(smem + S_AT);

    float* out = mode ? g_l_paper : g_l_author;
    float* alA = mode ? g_asrc_c : g_asrc_w;

    const int tid  = threadIdx.x;
    const int lane = tid & 31;
    const int wp   = tid >> 5;           // 8 warps; warp wp owns rows [wp*16, wp*16+16)
    const int g    = lane >> 2;          // fragment row group 0..7
    const int q    = lane & 3;           // fragment k/col quad
    const int row0 = blockIdx.x * 128;

    if (tid < 64) {
        bs[tid]  = bias[tid];
        as_[tid] = attn[(tid >> 4) * (2 * C) + C + (tid & 15)];
    }

    float acc[8][4];
    #pragma unroll
    for (int i = 0; i < 8; i++) {
        #pragma unroll
        for (int j = 0; j < 4; j++) acc[i][j] = 0.f;
    }

    for (int c = 0; c < DIN / KCH; c++) {
        const int kc = c * KCH;
        __syncthreads();
        // A chunk: 128 rows x 32 k  (coalesced float4 loads, split to hi/lo)
        #pragma unroll
        for (int i = 0; i < 4; i++) {
            int idx = i * 256 + tid;
            int r = idx >> 3, kq = idx & 7;
            int gr = row0 + r;
            float4 f = (gr < N) ? *(const float4*)(A + (size_t)gr * DIN + kc + kq * 4)
                                : make_float4(0.f, 0.f, 0.f, 0.f);
            uint32_t h0, l0, h1, l1;
            split2(f.x, f.y, h0, l0);
            split2(f.z, f.w, h1, l1);
            *(uint2*)(Ah + r * APAD + kq * 4) = make_uint2(h0, h1);
            *(uint2*)(Al + r * APAD + kq * 4) = make_uint2(l0, l1);
        }
        // W chunk transposed: Ws[n][k] = W[kc+k][n]
        #pragma unroll
        for (int i = 0; i < 2; i++) {
            int idx = i * 256 + tid;
            int n = idx >> 3, kq = idx & 7;
            float f0 = W[(kc + kq * 4 + 0) * DOUT + n];
            float f1 = W[(kc + kq * 4 + 1) * DOUT + n];
            float f2 = W[(kc + kq * 4 + 2) * DOUT + n];
            float f3 = W[(kc + kq * 4 + 3) * DOUT + n];
            uint32_t h0, l0, h1, l1;
            split2(f0, f1, h0, l0);
            split2(f2, f3, h1, l1);
            *(uint2*)(Wh + n * APAD + kq * 4) = make_uint2(h0, h1);
            *(uint2*)(Wl + n * APAD + kq * 4) = make_uint2(l0, l1);
        }
        __syncthreads();

        const __nv_bfloat16* Aps[3] = {Ah, Ah, Al};
        const __nv_bfloat16* Bps[3] = {Wh, Wl, Wh};
        #pragma unroll
        for (int p = 0; p < 3; p++) {
            const __nv_bfloat16* Ap = Aps[p];
            const __nv_bfloat16* Bp = Bps[p];
            #pragma unroll
            for (int ks = 0; ks < KCH; ks += 16) {
                uint32_t a0 = *(const uint32_t*)(Ap + (wp * 16 + g)     * APAD + ks + q * 2);
                uint32_t a1 = *(const uint32_t*)(Ap + (wp * 16 + g + 8) * APAD + ks + q * 2);
                uint32_t a2 = *(const uint32_t*)(Ap + (wp * 16 + g)     * APAD + ks + q * 2 + 8);
                uint32_t a3 = *(const uint32_t*)(Ap + (wp * 16 + g + 8) * APAD + ks + q * 2 + 8);
                #pragma unroll
                for (int nt = 0; nt < 8; nt++) {
                    uint32_t b0 = *(const uint32_t*)(Bp + (nt * 8 + g) * APAD + ks + q * 2);
                    uint32_t b1 = *(const uint32_t*)(Bp + (nt * 8 + g) * APAD + ks + q * 2 + 8);
                    mma16816(acc[nt], a0, a1, a2, a3, b0, b1);
                }
            }
        }
    }

    // stage accumulators to smem (fp32, padded stride 66; float2 granularity ONLY —
    // stride 66 floats = 264 B is 8B- but not 16B-aligned for odd rows, so no float4 here)
    __syncthreads();
    float* Os = (float*)(smem + S_OS);
    #pragma unroll
    for (int nt = 0; nt < 8; nt++) {
        int r = wp * 16 + g, cl = nt * 8 + q * 2;
        *(float2*)(Os + r * 66 + cl)       = make_float2(acc[nt][0], acc[nt][1]);
        *(float2*)(Os + (r + 8) * 66 + cl) = make_float2(acc[nt][2], acc[nt][3]);
    }
    __syncthreads();

    // coalesced writeback + fused alpha_src (2 threads per row, 32 cols each)
    {
        int r = tid >> 1, hf = tid & 1;
        int gr = row0 + r;
        if (gr < N) {
            float ph0 = 0.f, ph1 = 0.f;
            float* op = out + (size_t)gr * DOUT + hf * 32;
            #pragma unroll
            for (int j = 0; j < 8; j++) {
                int cb = hf * 32 + j * 4;
                float2 va = *(float2*)(Os + r * 66 + cb);       // 8B-aligned: OK
                float2 vb = *(float2*)(Os + r * 66 + cb + 2);
                float4 v = make_float4(va.x, va.y, vb.x, vb.y);
                v.x += bs[cb + 0]; v.y += bs[cb + 1];
                v.z += bs[cb + 2]; v.w += bs[cb + 3];
                *(float4*)(op + j * 4) = v;                     // GMEM, 16B-aligned
                float d = fmaxf(v.x, 0.2f * v.x) * as_[cb + 0]
                        + fmaxf(v.y, 0.2f * v.y) * as_[cb + 1]
                        + fmaxf(v.z, 0.2f * v.z) * as_[cb + 2]
                        + fmaxf(v.w, 0.2f * v.w) * as_[cb + 3];
                if (j < 4) ph0 += d; else ph1 += d;
            }
            // heads hf*2 and hf*2+1
            *(float2*)(alA + (size_t)gr * H + hf * 2) = make_float2(ph0, ph1);
        }
    }
}

// ---------------------------------------------------------------------------
// K0: zero edge counters
// ---------------------------------------------------------------------------
__global__ void k_zero() {
    int i = blockIdx.x * 256 + threadIdx.x;
    if (i < 2 * NOUT) (&g_cnt[0][0])[i] = 0;
}

// ---------------------------------------------------------------------------
// K2: histogram both relations in one pass
// ---------------------------------------------------------------------------
__global__ void k_hist2(const int* __restrict__ d0, const int* __restrict__ d1) {
    int i = blockIdx.x * 256 + threadIdx.x;
    if (i >= E) return;
    atomicAdd(&g_cnt[0][d0[i]], 1);
    atomicAdd(&g_cnt[1][d1[i]], 1);
}

// ---------------------------------------------------------------------------
// K3: exclusive scan (one block per relation)
// ---------------------------------------------------------------------------
__global__ void k_scan() {
    __shared__ int sh[1024];
    const int rel = blockIdx.x;
    const int CH = (NOUT + 1023) / 1024;
    int t = threadIdx.x;
    int s0 = t * CH;
    int s1 = s0 + CH; if (s1 > NOUT) s1 = NOUT;
    int sum = 0;
    for (int i = s0; i < s1; i++) sum += g_cnt[rel][i];
    sh[t] = sum;
    __syncthreads();
    for (int o = 1; o < 1024; o <<= 1) {
        int v = (t >= o) ? sh[t - o] : 0;
        __syncthreads();
        sh[t] += v;
        __syncthreads();
    }
    int base = sh[t] - sum;
    for (int i = s0; i < s1; i++) {
        g_off[rel][i] = base;
        g_cur[rel][i] = base;
        base += g_cnt[rel][i];
    }
    if (s0 < NOUT && s1 == NOUT) g_off[rel][NOUT] = base;
}

// ---------------------------------------------------------------------------
// K4: scatter both relations into CSR (source index only)
// ---------------------------------------------------------------------------
__global__ void k_scatter2(const int* __restrict__ s0, const int* __restrict__ d0,
                           const int* __restrict__ s1, const int* __restrict__ d1) {
    int i = blockIdx.x * 256 + threadIdx.x;
    if (i >= E) return;
    int p0 = atomicAdd(&g_cur[0][d0[i]], 1);
    g_csrc[0][p0] = s0[i];
    int p1 = atomicAdd(&g_cur[1][d1[i]], 1);
    g_csrc[1][p1] = s1[i];
}

// ---------------------------------------------------------------------------
// K5: per-destination softmax aggregation. One warp per destination.
//     Phase 1: edge-parallel online max/sum (8 lanes per head) + shfl merge.
//     Phase 2: per-edge coalesced 256B feature gather, weighted accumulate.
// ---------------------------------------------------------------------------
__global__ __launch_bounds__(256) void k_agg() {
    const int rel = blockIdx.y;
    const float* __restrict__ lsrc = rel ? g_l_paper : g_l_author;
    const float* __restrict__ asrc = rel ? g_asrc_c : g_asrc_w;
    const int* off  = g_off[rel];
    const int* csrc = g_csrc[rel];
    float*     emb  = g_emb[rel];

    int w = blockIdx.x * 8 + (threadIdx.x >> 5);
    if (w >= NOUT) return;
    int lane = threadIdx.x & 31;
    int h = lane >> 3, sub = lane & 7;

    int beg = off[w], end = off[w + 1];

    // phase 1: online softmax stats, edges strided across the 8 lanes of each head
    float m = -1e30f, s = 0.f;
    for (int e = beg + sub; e < end; e += 8) {
        float v = asrc[(size_t)csrc[e] * H + h];
        if (v > m) { s *= __expf(m - v); m = v; }
        s += __expf(v - m);
    }
    #pragma unroll
    for (int o = 1; o < 8; o <<= 1) {
        float mo = __shfl_xor_sync(0xffffffffu, m, o);
        float so = __shfl_xor_sync(0xffffffffu, s, o);
        float mn = fmaxf(m, mo);
        s = s * __expf(m - mn) + so * __expf(mo - mn);
        m = mn;
    }

    // phase 2: weighted gather
    float a0 = 0.f, a1 = 0.f;
    #pragma unroll 4
    for (int e = beg; e < end; e++) {
        int srci = csrc[e];
        float wg = __expf(asrc[(size_t)srci * H + h] - m);
        float2 xj = *(const float2*)&lsrc[(size_t)srci * DOUT + lane * 2];
        a0 += wg * xj.x;
        a1 += wg * xj.y;
    }
    float inv = 1.f / (s + 1e-16f);
    *(float2*)&emb[(size_t)w * DOUT + lane * 2] = make_float2(a0 * inv, a1 * inv);
}

// ---------------------------------------------------------------------------
// K6: semantic attention over {writes, cites, self} + relu. Warp per node.
// ---------------------------------------------------------------------------
__global__ __launch_bounds__(256) void k_final(
    const float* __restrict__ rel_l, const float* __restrict__ rel_r,
    float* __restrict__ outp)
{
    int n = blockIdx.x * 8 + (threadIdx.x >> 5);
    if (n >= NOUT) return;
    int lane = threadIdx.x & 31;
    int h  = lane >> 3;
    int c0 = lane * 2;
    int ci = c0 & 15;

    float2 ew = *(const float2*)&g_emb[0][(size_t)n * DOUT + c0];
    float2 ec = *(const float2*)&g_emb[1][(size_t)n * DOUT + c0];
    float2 es = *(const float2*)&g_l_paper[(size_t)n * DOUT + c0];

    float al = es.x * __ldg(&rel_l[h * C + ci]) + es.y * __ldg(&rel_l[h * C + ci + 1]);
    float r0 = ew.x * __ldg(&rel_r[0 * H * C + h * C + ci]) + ew.y * __ldg(&rel_r[0 * H * C + h * C + ci + 1]);
    float r1 = ec.x * __ldg(&rel_r[1 * H * C + h * C + ci]) + ec.y * __ldg(&rel_r[1 * H * C + h * C + ci + 1]);
    float r2 = es.x * __ldg(&rel_r[2 * H * C + h * C + ci]) + es.y * __ldg(&rel_r[2 * H * C + h * C + ci + 1]);

    #pragma unroll
    for (int o = 1; o <= 4; o <<= 1) {
        al += __shfl_xor_sync(0xffffffffu, al, o);
        r0 += __shfl_xor_sync(0xffffffffu, r0, o);
        r1 += __shfl_xor_sync(0xffffffffu, r1, o);
        r2 += __shfl_xor_sync(0xffffffffu, r2, o);
    }

    float x0 = al + r0; x0 = fmaxf(x0, 0.2f * x0);
    float x1 = al + r1; x1 = fmaxf(x1, 0.2f * x1);
    float x2 = al + r2; x2 = fmaxf(x2, 0.2f * x2);
    float mx = fmaxf(x0, fmaxf(x1, x2));
    float e0 = __expf(x0 - mx), e1 = __expf(x1 - mx), e2 = __expf(x2 - mx);
    float ib = 1.f / (e0 + e1 + e2);
    float b0 = e0 * ib, b1 = e1 * ib, b2 = e2 * ib;

    float o0 = fmaxf(ew.x * b0 + ec.x * b1 + es.x * b2, 0.f);
    float o1 = fmaxf(ew.y * b0 + ec.y * b1 + es.y * b2, 0.f);
    *(float2*)&outp[(size_t)n * DOUT + c0] = make_float2(o0, o1);
}

// ---------------------------------------------------------------------------
// Launch
// ---------------------------------------------------------------------------
extern "C" void kernel_launch(void* const* d_in, const int* in_sizes, int n_in,
                              void* d_out, int out_size) {
    (void)in_sizes; (void)out_size;
    if (n_in < 16) return;
    const float* x_author   = (const float*)d_in[0];
    const float* x_paper    = (const float*)d_in[1];
    const float* W_l_author = (const float*)d_in[2];
    const float* b_l_author = (const float*)d_in[3];
    const float* W_l_paper  = (const float*)d_in[4];
    const float* b_l_paper  = (const float*)d_in[5];
    // d_in[6], d_in[7] (W_r_paper, b_r_paper): softmax-invariant -> unused
    const float* attn_w     = (const float*)d_in[8];
    const float* attn_c     = (const float*)d_in[9];
    const float* rel_l      = (const float*)d_in[10];
    const float* rel_r      = (const float*)d_in[11];
    const int*   src_w      = (const int*)d_in[12];
    const int*   dst_w      = (const int*)d_in[13];
    const int*   src_c      = (const int*)d_in[14];
    const int*   dst_c      = (const int*)d_in[15];
    float* outp = (float*)d_out;

    k_zero<<<(2 * NOUT + 255) / 256, 256>>>();
    k_hist2<<<(E + 255) / 256, 256>>>(dst_w, dst_c);
    k_scan<<<2, 1024>>>();
    k_scatter2<<<(E + 255) / 256, 256>>>(src_w, dst_w, src_c, dst_c);
    k_gemm_mma<<<(NA + 127) / 128, 256>>>(x_author, NA, W_l_author, b_l_author, attn_w, 0);
    k_gemm_mma<<<(NP + 127) / 128, 256>>>(x_paper,  NP, W_l_paper,  b_l_paper,  attn_c, 1);
    k_agg<<<dim3((NOUT + 7) / 8, 2), 256>>>();
    k_final<<<(NOUT + 7) / 8, 256>>>(rel_l, rel_r, outp);
}

// round 7
// speedup vs baseline: 1.5664x; 1.0878x over previous
#include <cuda_runtime.h>
#include <cuda_bf16.h>
#include <cstdint>

// ---------------------------------------------------------------------------
// Problem constants
// ---------------------------------------------------------------------------
constexpr int H    = 4;
constexpr int C    = 16;
constexpr int DIN  = 128;
constexpr int DOUT = 64;
constexpr int NA   = 150000;
constexpr int NP   = 200000;
constexpr int NOUT = 50000;
constexpr int E    = 1000000;

// ---------------------------------------------------------------------------
// Device scratch (static; no allocations allowed)
// ---------------------------------------------------------------------------
__device__ __align__(16) float g_l_author[(size_t)NA * DOUT];   // 38.4 MB
__device__ __align__(16) float g_l_paper [(size_t)NP * DOUT];   // 51.2 MB
// easrc = exp(alpha_src) per (node, head). Logits are O(1) (std ~0.34), so exp
// never overflows; softmax shift-invariance makes the reference's segment-max
// cancel exactly. Storing exp() kills k_agg's entire max/merge phase.
__device__ __align__(16) float g_easrc_w [(size_t)NA * H];
__device__ __align__(16) float g_easrc_c [(size_t)NP * H];
__device__ int g_cnt [2][NOUT];
__device__ int g_off [2][NOUT + 1];
__device__ int g_cur [2][NOUT];
__device__ int g_csrc[2][E];
__device__ __align__(16) float g_emb[2][(size_t)NOUT * DOUT];

// fp32 -> (bf16 hi, bf16 lo residual) packed pairs
__device__ __forceinline__ void split2(float a, float b, uint32_t& hi, uint32_t& lo) {
    __nv_bfloat162 h = __floats2bfloat162_rn(a, b);
    float2 hf = __bfloat1622float2(h);
    __nv_bfloat162 l = __floats2bfloat162_rn(a - hf.x, b - hf.y);
    hi = *(uint32_t*)&h;
    lo = *(uint32_t*)&l;
}

__device__ __forceinline__ void mma16816(float* c, uint32_t a0, uint32_t a1, uint32_t a2,
                                         uint32_t a3, uint32_t b0, uint32_t b1) {
    asm volatile(
        "mma.sync.aligned.m16n8k16.row.col.f32.bf16.bf16.f32 "
        "{%0,%1,%2,%3}, {%4,%5,%6,%7}, {%8,%9}, {%0,%1,%2,%3};"
        : "+f"(c[0]), "+f"(c[1]), "+f"(c[2]), "+f"(c[3])
        : "r"(a0), "r"(a1), "r"(a2), "r"(a3), "r"(b0), "r"(b1));
}

// ---------------------------------------------------------------------------
// K1: bf16-split mma.sync GEMM  l = x @ W + b  (tile 128 rows x 64 cols / CTA)
//     3 passes: A_hi*W_hi + A_hi*W_lo + A_lo*W_hi  -> fp32 acc (err ~2^-16)
//     Software-pipelined: chunk c+1's GMEM loads issue before chunk c's MMAs.
//     Fused epilogue: bias, store l, easrc[n,h] = exp(sum_c lrelu(l)*attn[h,C+c])
// ---------------------------------------------------------------------------
constexpr int KCH   = 32;            // k-chunk
constexpr int APAD  = 40;            // row stride in halfs (32 + 8 pad) -> conflict-free
constexpr int S_AH  = 0;             // 128*40*2 = 10240
constexpr int S_AL  = 10240;
constexpr int S_WH  = 20480;         // 64*40*2 = 5120
constexpr int S_WL  = 25600;
constexpr int S_OS  = 0;             // output staging 128 x 66 fp32 = 33792 (reuses A/W)
constexpr int S_BS  = 33792;         // 64 floats bias
constexpr int S_AT  = 34048;         // 64 floats attn (col-indexed)
constexpr int GSMEM = 34304;

__global__ __launch_bounds__(256, 2) void k_gemm_mma(
    const float* __restrict__ A, int N,
    const float* __restrict__ W, const float* __restrict__ bias,
    const float* __restrict__ attn, int mode)
{
    __shared__ __align__(16) char smem[GSMEM];
    __nv_bfloat16* Ah = (__nv_bfloat16*)(smem + S_AH);
    __nv_bfloat16* Al = (__nv_bfloat16*)(smem + S_AL);
    __nv_bfloat16* Wh = (__nv_bfloat16*)(smem + S_WH);
    __nv_bfloat16* Wl = (__nv_bfloat16*)(smem + S_WL);
    float* bs  = (float*)(smem + S_BS);
    float* as_ = (float*)(smem + S_AT);

    float* out = mode ? g_l_paper : g_l_author;
    float* alA = mode ? g_easrc_c : g_easrc_w;

    const int tid  = threadIdx.x;
    const int lane = tid & 31;
    const int wp   = tid >> 5;           // 8 warps; warp wp owns rows [wp*16, wp*16+16)
    const int g    = lane >> 2;          // fragment row group 0..7
    const int q    = lane & 3;           // fragment k/col quad
    const int row0 = blockIdx.x * 128;

    // per-thread load coordinates (fixed across chunks)
    const int lrA = (tid >> 3);          // A row for i=0 (then +32 per i)
    const int lkA = (tid & 7) * 4;       // A k-offset within chunk
    const int lnW = (tid >> 3);          // W col for i=0 (then +32 for i=1)
    const int lkW = (tid & 7) * 4;       // W k-offset within chunk

    if (tid < 64) {
        bs[tid]  = bias[tid];
        as_[tid] = attn[(tid >> 4) * (2 * C) + C + (tid & 15)];
    }

    float acc[8][4];
    #pragma unroll
    for (int i = 0; i < 8; i++) {
        #pragma unroll
        for (int j = 0; j < 4; j++) acc[i][j] = 0.f;
    }

    float4 fa[4];
    float  fw[2][4];

    auto load_chunk = [&](int kc) {
        #pragma unroll
        for (int i = 0; i < 4; i++) {
            int gr = row0 + lrA + i * 32;
            fa[i] = (gr < N) ? *(const float4*)(A + (size_t)gr * DIN + kc + lkA)
                             : make_float4(0.f, 0.f, 0.f, 0.f);
        }
        #pragma unroll
        for (int i = 0; i < 2; i++) {
            int n = lnW + i * 32;
            #pragma unroll
            for (int j = 0; j < 4; j++)
                fw[i][j] = W[(kc + lkW + j) * DOUT + n];
        }
    };
    auto store_chunk = [&]() {
        #pragma unroll
        for (int i = 0; i < 4; i++) {
            int r = lrA + i * 32;
            uint32_t h0, l0, h1, l1;
            split2(fa[i].x, fa[i].y, h0, l0);
            split2(fa[i].z, fa[i].w, h1, l1);
            *(uint2*)(Ah + r * APAD + lkA) = make_uint2(h0, h1);
            *(uint2*)(Al + r * APAD + lkA) = make_uint2(l0, l1);
        }
        #pragma unroll
        for (int i = 0; i < 2; i++) {
            int n = lnW + i * 32;
            uint32_t h0, l0, h1, l1;
            split2(fw[i][0], fw[i][1], h0, l0);
            split2(fw[i][2], fw[i][3], h1, l1);
            *(uint2*)(Wh + n * APAD + lkW) = make_uint2(h0, h1);
            *(uint2*)(Wl + n * APAD + lkW) = make_uint2(l0, l1);
        }
    };

    load_chunk(0);                                   // prologue
    for (int c = 0; c < DIN / KCH; c++) {
        store_chunk();                               // convert regs -> smem
        __syncthreads();
        if (c + 1 < DIN / KCH) load_chunk((c + 1) * KCH);   // LDGs in flight during MMA

        const __nv_bfloat16* Aps[3] = {Ah, Ah, Al};
        const __nv_bfloat16* Bps[3] = {Wh, Wl, Wh};
        #pragma unroll
        for (int p = 0; p < 3; p++) {
            const __nv_bfloat16* Ap = Aps[p];
            const __nv_bfloat16* Bp = Bps[p];
            #pragma unroll
            for (int ks = 0; ks < KCH; ks += 16) {
                uint32_t a0 = *(const uint32_t*)(Ap + (wp * 16 + g)     * APAD + ks + q * 2);
                uint32_t a1 = *(const uint32_t*)(Ap + (wp * 16 + g + 8) * APAD + ks + q * 2);
                uint32_t a2 = *(const uint32_t*)(Ap + (wp * 16 + g)     * APAD + ks + q * 2 + 8);
                uint32_t a3 = *(const uint32_t*)(Ap + (wp * 16 + g + 8) * APAD + ks + q * 2 + 8);
                #pragma unroll
                for (int nt = 0; nt < 8; nt++) {
                    uint32_t b0 = *(const uint32_t*)(Bp + (nt * 8 + g) * APAD + ks + q * 2);
                    uint32_t b1 = *(const uint32_t*)(Bp + (nt * 8 + g) * APAD + ks + q * 2 + 8);
                    mma16816(acc[nt], a0, a1, a2, a3, b0, b1);
                }
            }
        }
        __syncthreads();                             // smem free before next store
    }

    // stage accumulators to smem (fp32, padded stride 66; float2 granularity ONLY —
    // stride 66 floats = 264 B is 8B- but not 16B-aligned for odd rows, so no float4 here)
    float* Os = (float*)(smem + S_OS);
    #pragma unroll
    for (int nt = 0; nt < 8; nt++) {
        int r = wp * 16 + g, cl = nt * 8 + q * 2;
        *(float2*)(Os + r * 66 + cl)       = make_float2(acc[nt][0], acc[nt][1]);
        *(float2*)(Os + (r + 8) * 66 + cl) = make_float2(acc[nt][2], acc[nt][3]);
    }
    __syncthreads();

    // coalesced writeback + fused exp(alpha_src) (2 threads per row, 32 cols each)
    {
        int r = tid >> 1, hf = tid & 1;
        int gr = row0 + r;
        if (gr < N) {
            float ph0 = 0.f, ph1 = 0.f;
            float* op = out + (size_t)gr * DOUT + hf * 32;
            #pragma unroll
            for (int j = 0; j < 8; j++) {
                int cb = hf * 32 + j * 4;
                float2 va = *(float2*)(Os + r * 66 + cb);       // 8B-aligned: OK
                float2 vb = *(float2*)(Os + r * 66 + cb + 2);
                float4 v = make_float4(va.x, va.y, vb.x, vb.y);
                v.x += bs[cb + 0]; v.y += bs[cb + 1];
                v.z += bs[cb + 2]; v.w += bs[cb + 3];
                *(float4*)(op + j * 4) = v;                     // GMEM, 16B-aligned
                float d = fmaxf(v.x, 0.2f * v.x) * as_[cb + 0]
                        + fmaxf(v.y, 0.2f * v.y) * as_[cb + 1]
                        + fmaxf(v.z, 0.2f * v.z) * as_[cb + 2]
                        + fmaxf(v.w, 0.2f * v.w) * as_[cb + 3];
                if (j < 4) ph0 += d; else ph1 += d;
            }
            // heads hf*2 and hf*2+1; store exp(alpha) directly
            *(float2*)(alA + (size_t)gr * H + hf * 2) =
                make_float2(__expf(ph0), __expf(ph1));
        }
    }
}

// ---------------------------------------------------------------------------
// K0: zero edge counters
// ---------------------------------------------------------------------------
__global__ void k_zero() {
    int i = blockIdx.x * 256 + threadIdx.x;
    if (i < 2 * NOUT) (&g_cnt[0][0])[i] = 0;
}

// ---------------------------------------------------------------------------
// K2: histogram both relations in one pass
// ---------------------------------------------------------------------------
__global__ void k_hist2(const int* __restrict__ d0, const int* __restrict__ d1) {
    int i = blockIdx.x * 256 + threadIdx.x;
    if (i >= E) return;
    atomicAdd(&g_cnt[0][d0[i]], 1);
    atomicAdd(&g_cnt[1][d1[i]], 1);
}

// ---------------------------------------------------------------------------
// K3: exclusive scan (one block per relation)
// ---------------------------------------------------------------------------
__global__ void k_scan() {
    __shared__ int sh[1024];
    const int rel = blockIdx.x;
    const int CH = (NOUT + 1023) / 1024;
    int t = threadIdx.x;
    int s0 = t * CH;
    int s1 = s0 + CH; if (s1 > NOUT) s1 = NOUT;
    int sum = 0;
    for (int i = s0; i < s1; i++) sum += g_cnt[rel][i];
    sh[t] = sum;
    __syncthreads();
    for (int o = 1; o < 1024; o <<= 1) {
        int v = (t >= o) ? sh[t - o] : 0;
        __syncthreads();
        sh[t] += v;
        __syncthreads();
    }
    int base = sh[t] - sum;
    for (int i = s0; i < s1; i++) {
        g_off[rel][i] = base;
        g_cur[rel][i] = base;
        base += g_cnt[rel][i];
    }
    if (s0 < NOUT && s1 == NOUT) g_off[rel][NOUT] = base;
}

// ---------------------------------------------------------------------------
// K4: scatter both relations into CSR (source index only)
// ---------------------------------------------------------------------------
__global__ void k_scatter2(const int* __restrict__ s0, const int* __restrict__ d0,
                           const int* __restrict__ s1, const int* __restrict__ d1) {
    int i = blockIdx.x * 256 + threadIdx.x;
    if (i >= E) return;
    int p0 = atomicAdd(&g_cur[0][d0[i]], 1);
    g_csrc[0][p0] = s0[i];
    int p1 = atomicAdd(&g_cur[1][d1[i]], 1);
    g_csrc[1][p1] = s1[i];
}

// ---------------------------------------------------------------------------
// K5: per-destination softmax aggregation. One warp per destination.
//     Single pass (no max shift needed: logits are O(1), exp precomputed in
//     GEMM epilogue). Per edge: 16B easrc line + 256B coalesced feature row.
// ---------------------------------------------------------------------------
__global__ __launch_bounds__(256) void k_agg() {
    const int rel = blockIdx.y;
    const float* __restrict__ lsrc  = rel ? g_l_paper : g_l_author;
    const float* __restrict__ easrc = rel ? g_easrc_c : g_easrc_w;
    const int* off  = g_off[rel];
    const int* csrc = g_csrc[rel];
    float*     emb  = g_emb[rel];

    int w = blockIdx.x * 8 + (threadIdx.x >> 5);
    if (w >= NOUT) return;
    int lane = threadIdx.x & 31;
    int h = lane >> 3;

    int beg = off[w], end = off[w + 1];

    float s = 0.f, a0 = 0.f, a1 = 0.f;
    #pragma unroll 4
    for (int e = beg; e < end; e++) {
        int srci = csrc[e];
        float wg = easrc[(size_t)srci * H + h];
        float2 xj = *(const float2*)&lsrc[(size_t)srci * DOUT + lane * 2];
        s  += wg;
        a0 += wg * xj.x;
        a1 += wg * xj.y;
    }
    float inv = 1.f / (s + 1e-16f);
    *(float2*)&emb[(size_t)w * DOUT + lane * 2] = make_float2(a0 * inv, a1 * inv);
}

// ---------------------------------------------------------------------------
// K6: semantic attention over {writes, cites, self} + relu. Warp per node.
// ---------------------------------------------------------------------------
__global__ __launch_bounds__(256) void k_final(
    const float* __restrict__ rel_l, const float* __restrict__ rel_r,
    float* __restrict__ outp)
{
    int n = blockIdx.x * 8 + (threadIdx.x >> 5);
    if (n >= NOUT) return;
    int lane = threadIdx.x & 31;
    int h  = lane >> 3;
    int c0 = lane * 2;
    int ci = c0 & 15;

    float2 ew = *(const float2*)&g_emb[0][(size_t)n * DOUT + c0];
    float2 ec = *(const float2*)&g_emb[1][(size_t)n * DOUT + c0];
    float2 es = *(const float2*)&g_l_paper[(size_t)n * DOUT + c0];

    float al = es.x * __ldg(&rel_l[h * C + ci]) + es.y * __ldg(&rel_l[h * C + ci + 1]);
    float r0 = ew.x * __ldg(&rel_r[0 * H * C + h * C + ci]) + ew.y * __ldg(&rel_r[0 * H * C + h * C + ci + 1]);
    float r1 = ec.x * __ldg(&rel_r[1 * H * C + h * C + ci]) + ec.y * __ldg(&rel_r[1 * H * C + h * C + ci + 1]);
    float r2 = es.x * __ldg(&rel_r[2 * H * C + h * C + ci]) + es.y * __ldg(&rel_r[2 * H * C + h * C + ci + 1]);

    #pragma unroll
    for (int o = 1; o <= 4; o <<= 1) {
        al += __shfl_xor_sync(0xffffffffu, al, o);
        r0 += __shfl_xor_sync(0xffffffffu, r0, o);
        r1 += __shfl_xor_sync(0xffffffffu, r1, o);
        r2 += __shfl_xor_sync(0xffffffffu, r2, o);
    }

    float x0 = al + r0; x0 = fmaxf(x0, 0.2f * x0);
    float x1 = al + r1; x1 = fmaxf(x1, 0.2f * x1);
    float x2 = al + r2; x2 = fmaxf(x2, 0.2f * x2);
    float mx = fmaxf(x0, fmaxf(x1, x2));
    float e0 = __expf(x0 - mx), e1 = __expf(x1 - mx), e2 = __expf(x2 - mx);
    float ib = 1.f / (e0 + e1 + e2);
    float b0 = e0 * ib, b1 = e1 * ib, b2 = e2 * ib;

    float o0 = fmaxf(ew.x * b0 + ec.x * b1 + es.x * b2, 0.f);
    float o1 = fmaxf(ew.y * b0 + ec.y * b1 + es.y * b2, 0.f);
    *(float2*)&outp[(size_t)n * DOUT + c0] = make_float2(o0, o1);
}

// ---------------------------------------------------------------------------
// Launch
// ---------------------------------------------------------------------------
extern "C" void kernel_launch(void* const* d_in, const int* in_sizes, int n_in,
                              void* d_out, int out_size) {
    (void)in_sizes; (void)out_size;
    if (n_in < 16) return;
    const float* x_author   = (const float*)d_in[0];
    const float* x_paper    = (const float*)d_in[1];
    const float* W_l_author = (const float*)d_in[2];
    const float* b_l_author = (const float*)d_in[3];
    const float* W_l_paper  = (const float*)d_in[4];
    const float* b_l_paper  = (const float*)d_in[5];
    // d_in[6], d_in[7] (W_r_paper, b_r_paper): softmax-invariant -> unused
    const float* attn_w     = (const float*)d_in[8];
    const float* attn_c     = (const float*)d_in[9];
    const float* rel_l      = (const float*)d_in[10];
    const float* rel_r      = (const float*)d_in[11];
    const int*   src_w      = (const int*)d_in[12];
    const int*   dst_w      = (const int*)d_in[13];
    const int*   src_c      = (const int*)d_in[14];
    const int*   dst_c      = (const int*)d_in[15];
    float* outp = (float*)d_out;

    k_zero<<<(2 * NOUT + 255) / 256, 256>>>();
    k_hist2<<<(E + 255) / 256, 256>>>(dst_w, dst_c);
    k_scan<<<2, 1024>>>();
    k_scatter2<<<(E + 255) / 256, 256>>>(src_w, dst_w, src_c, dst_c);
    k_gemm_mma<<<(NA + 127) / 128, 256>>>(x_author, NA, W_l_author, b_l_author, attn_w, 0);
    k_gemm_mma<<<(NP + 127) / 128, 256>>>(x_paper,  NP, W_l_paper,  b_l_paper,  attn_c, 1);
    k_agg<<<dim3((NOUT + 7) / 8, 2), 256>>>();
    k_final<<<(NOUT + 7) / 8, 256>>>(rel_l, rel_r, outp);
}

// round 8
// speedup vs baseline: 2.0475x; 1.3071x over previous
#include <cuda_runtime.h>
#include <cuda_bf16.h>
#include <cstdint>

// ---------------------------------------------------------------------------
// Problem constants
// ---------------------------------------------------------------------------
constexpr int H    = 4;
constexpr int C    = 16;
constexpr int DIN  = 128;
constexpr int DOUT = 64;
constexpr int NA   = 150000;
constexpr int NP   = 200000;
constexpr int NOUT = 50000;
constexpr int E    = 1000000;
constexpr int SCB  = (NOUT + 1023) / 1024;   // 49 scan blocks per relation

// ---------------------------------------------------------------------------
// Device scratch (static; no allocations allowed)
// ---------------------------------------------------------------------------
__device__ __align__(16) float g_l_author[(size_t)NA * DOUT];   // 38.4 MB
__device__ __align__(16) float g_l_paper [(size_t)NP * DOUT];   // 51.2 MB
// easrc = exp(alpha_src) per (node, head). Logits are O(1) (std ~0.34), so exp
// never overflows; softmax shift-invariance makes the reference's segment-max
// cancel exactly. Storing exp() kills the aggregation max/merge phase.
__device__ __align__(16) float g_easrc_w [(size_t)NA * H];
__device__ __align__(16) float g_easrc_c [(size_t)NP * H];
__device__ int g_cnt [2][NOUT];
__device__ int g_off [2][NOUT + 1];
__device__ int g_cur [2][NOUT];
__device__ int g_csrc[2][E];
__device__ int g_part [2][64];
__device__ int g_pbase[2][64];

// fp32 -> (bf16 hi, bf16 lo residual) packed pairs
__device__ __forceinline__ void split2(float a, float b, uint32_t& hi, uint32_t& lo) {
    __nv_bfloat162 h = __floats2bfloat162_rn(a, b);
    float2 hf = __bfloat1622float2(h);
    __nv_bfloat162 l = __floats2bfloat162_rn(a - hf.x, b - hf.y);
    hi = *(uint32_t*)&h;
    lo = *(uint32_t*)&l;
}

__device__ __forceinline__ void mma16816(float* c, uint32_t a0, uint32_t a1, uint32_t a2,
                                         uint32_t a3, uint32_t b0, uint32_t b1) {
    asm volatile(
        "mma.sync.aligned.m16n8k16.row.col.f32.bf16.bf16.f32 "
        "{%0,%1,%2,%3}, {%4,%5,%6,%7}, {%8,%9}, {%0,%1,%2,%3};"
        : "+f"(c[0]), "+f"(c[1]), "+f"(c[2]), "+f"(c[3])
        : "r"(a0), "r"(a1), "r"(a2), "r"(a3), "r"(b0), "r"(b1));
}

// ---------------------------------------------------------------------------
// K1: bf16-split mma.sync GEMM  l = x @ W + b  (tile 128 rows x 64 cols / CTA)
//     3 passes: A_hi*W_hi + A_hi*W_lo + A_lo*W_hi  -> fp32 acc (err ~2^-16)
//     Software-pipelined; fused epilogue stores l and exp(alpha_src).
// ---------------------------------------------------------------------------
constexpr int KCH   = 32;
constexpr int APAD  = 40;            // row stride in halfs (32 + 8 pad) -> conflict-free
constexpr int S_AH  = 0;
constexpr int S_AL  = 10240;
constexpr int S_WH  = 20480;
constexpr int S_WL  = 25600;
constexpr int S_OS  = 0;             // output staging 128 x 66 fp32 (reuses A/W)
constexpr int S_BS  = 33792;
constexpr int S_AT  = 34048;
constexpr int GSMEM = 34304;

__global__ __launch_bounds__(256, 2) void k_gemm_mma(
    const float* __restrict__ A, int N,
    const float* __restrict__ W, const float* __restrict__ bias,
    const float* __restrict__ attn, int mode)
{
    __shared__ __align__(16) char smem[GSMEM];
    __nv_bfloat16* Ah = (__nv_bfloat16*)(smem + S_AH);
    __nv_bfloat16* Al = (__nv_bfloat16*)(smem + S_AL);
    __nv_bfloat16* Wh = (__nv_bfloat16*)(smem + S_WH);
    __nv_bfloat16* Wl = (__nv_bfloat16*)(smem + S_WL);
    float* bs  = (float*)(smem + S_BS);
    float* as_ = (float*)(smem + S_AT);

    float* out = mode ? g_l_paper : g_l_author;
    float* alA = mode ? g_easrc_c : g_easrc_w;

    const int tid  = threadIdx.x;
    const int lane = tid & 31;
    const int wp   = tid >> 5;
    const int g    = lane >> 2;
    const int q    = lane & 3;
    const int row0 = blockIdx.x * 128;

    const int lrA = (tid >> 3);
    const int lkA = (tid & 7) * 4;
    const int lnW = (tid >> 3);
    const int lkW = (tid & 7) * 4;

    if (tid < 64) {
        bs[tid]  = bias[tid];
        as_[tid] = attn[(tid >> 4) * (2 * C) + C + (tid & 15)];
    }

    float acc[8][4];
    #pragma unroll
    for (int i = 0; i < 8; i++) {
        #pragma unroll
        for (int j = 0; j < 4; j++) acc[i][j] = 0.f;
    }

    float4 fa[4];
    float  fw[2][4];

    auto load_chunk = [&](int kc) {
        #pragma unroll
        for (int i = 0; i < 4; i++) {
            int gr = row0 + lrA + i * 32;
            fa[i] = (gr < N) ? *(const float4*)(A + (size_t)gr * DIN + kc + lkA)
                             : make_float4(0.f, 0.f, 0.f, 0.f);
        }
        #pragma unroll
        for (int i = 0; i < 2; i++) {
            int n = lnW + i * 32;
            #pragma unroll
            for (int j = 0; j < 4; j++)
                fw[i][j] = W[(kc + lkW + j) * DOUT + n];
        }
    };
    auto store_chunk = [&]() {
        #pragma unroll
        for (int i = 0; i < 4; i++) {
            int r = lrA + i * 32;
            uint32_t h0, l0, h1, l1;
            split2(fa[i].x, fa[i].y, h0, l0);
            split2(fa[i].z, fa[i].w, h1, l1);
            *(uint2*)(Ah + r * APAD + lkA) = make_uint2(h0, h1);
            *(uint2*)(Al + r * APAD + lkA) = make_uint2(l0, l1);
        }
        #pragma unroll
        for (int i = 0; i < 2; i++) {
            int n = lnW + i * 32;
            uint32_t h0, l0, h1, l1;
            split2(fw[i][0], fw[i][1], h0, l0);
            split2(fw[i][2], fw[i][3], h1, l1);
            *(uint2*)(Wh + n * APAD + lkW) = make_uint2(h0, h1);
            *(uint2*)(Wl + n * APAD + lkW) = make_uint2(l0, l1);
        }
    };

    load_chunk(0);
    for (int c = 0; c < DIN / KCH; c++) {
        store_chunk();
        __syncthreads();
        if (c + 1 < DIN / KCH) load_chunk((c + 1) * KCH);

        const __nv_bfloat16* Aps[3] = {Ah, Ah, Al};
        const __nv_bfloat16* Bps[3] = {Wh, Wl, Wh};
        #pragma unroll
        for (int p = 0; p < 3; p++) {
            const __nv_bfloat16* Ap = Aps[p];
            const __nv_bfloat16* Bp = Bps[p];
            #pragma unroll
            for (int ks = 0; ks < KCH; ks += 16) {
                uint32_t a0 = *(const uint32_t*)(Ap + (wp * 16 + g)     * APAD + ks + q * 2);
                uint32_t a1 = *(const uint32_t*)(Ap + (wp * 16 + g + 8) * APAD + ks + q * 2);
                uint32_t a2 = *(const uint32_t*)(Ap + (wp * 16 + g)     * APAD + ks + q * 2 + 8);
                uint32_t a3 = *(const uint32_t*)(Ap + (wp * 16 + g + 8) * APAD + ks + q * 2 + 8);
                #pragma unroll
                for (int nt = 0; nt < 8; nt++) {
                    uint32_t b0 = *(const uint32_t*)(Bp + (nt * 8 + g) * APAD + ks + q * 2);
                    uint32_t b1 = *(const uint32_t*)(Bp + (nt * 8 + g) * APAD + ks + q * 2 + 8);
                    mma16816(acc[nt], a0, a1, a2, a3, b0, b1);
                }
            }
        }
        __syncthreads();
    }

    // stage accumulators to smem (stride 66 floats = 264B: 8B-aligned only -> float2)
    float* Os = (float*)(smem + S_OS);
    #pragma unroll
    for (int nt = 0; nt < 8; nt++) {
        int r = wp * 16 + g, cl = nt * 8 + q * 2;
        *(float2*)(Os + r * 66 + cl)       = make_float2(acc[nt][0], acc[nt][1]);
        *(float2*)(Os + (r + 8) * 66 + cl) = make_float2(acc[nt][2], acc[nt][3]);
    }
    __syncthreads();

    // coalesced writeback + fused exp(alpha_src)
    {
        int r = tid >> 1, hf = tid & 1;
        int gr = row0 + r;
        if (gr < N) {
            float ph0 = 0.f, ph1 = 0.f;
            float* op = out + (size_t)gr * DOUT + hf * 32;
            #pragma unroll
            for (int j = 0; j < 8; j++) {
                int cb = hf * 32 + j * 4;
                float2 va = *(float2*)(Os + r * 66 + cb);
                float2 vb = *(float2*)(Os + r * 66 + cb + 2);
                float4 v = make_float4(va.x, va.y, vb.x, vb.y);
                v.x += bs[cb + 0]; v.y += bs[cb + 1];
                v.z += bs[cb + 2]; v.w += bs[cb + 3];
                *(float4*)(op + j * 4) = v;
                float d = fmaxf(v.x, 0.2f * v.x) * as_[cb + 0]
                        + fmaxf(v.y, 0.2f * v.y) * as_[cb + 1]
                        + fmaxf(v.z, 0.2f * v.z) * as_[cb + 2]
                        + fmaxf(v.w, 0.2f * v.w) * as_[cb + 3];
                if (j < 4) ph0 += d; else ph1 += d;
            }
            *(float2*)(alA + (size_t)gr * H + hf * 2) =
                make_float2(__expf(ph0), __expf(ph1));
        }
    }
}

// ---------------------------------------------------------------------------
// K0: zero edge counters
// ---------------------------------------------------------------------------
__global__ void k_zero() {
    int i = blockIdx.x * 256 + threadIdx.x;
    if (i < 2 * NOUT) (&g_cnt[0][0])[i] = 0;
}

// ---------------------------------------------------------------------------
// K2: histogram both relations in one pass
// ---------------------------------------------------------------------------
__global__ void k_hist2(const int* __restrict__ d0, const int* __restrict__ d1) {
    int i = blockIdx.x * 256 + threadIdx.x;
    if (i >= E) return;
    atomicAdd(&g_cnt[0][d0[i]], 1);
    atomicAdd(&g_cnt[1][d1[i]], 1);
}

// ---------------------------------------------------------------------------
// K3a/b/c: parallel exclusive scan over counts (full-chip, 3 tiny phases)
// ---------------------------------------------------------------------------
__global__ void k_scanA() {                    // grid (SCB, 2), block 1024
    __shared__ int ws[32];
    int rel = blockIdx.y;
    int i = blockIdx.x * 1024 + threadIdx.x;
    int v = (i < NOUT) ? g_cnt[rel][i] : 0;
    int lane = threadIdx.x & 31, wid = threadIdx.x >> 5;
    #pragma unroll
    for (int o = 16; o > 0; o >>= 1) v += __shfl_xor_sync(0xffffffffu, v, o);
    if (lane == 0) ws[wid] = v;
    __syncthreads();
    if (wid == 0) {
        int x = ws[lane];
        #pragma unroll
        for (int o = 16; o > 0; o >>= 1) x += __shfl_xor_sync(0xffffffffu, x, o);
        if (lane == 0) g_part[rel][blockIdx.x] = x;
    }
}
__global__ void k_scanB() {                    // 1 block, 2 threads (one per rel)
    int rel = threadIdx.x;
    if (rel >= 2) return;
    int run = 0;
    for (int b = 0; b < SCB; b++) { g_pbase[rel][b] = run; run += g_part[rel][b]; }
    g_off[rel][NOUT] = run;                    // == E
}
__global__ void k_scanC() {                    // grid (SCB, 2), block 1024
    __shared__ int ws[32];
    int rel = blockIdx.y;
    int i = blockIdx.x * 1024 + threadIdx.x;
    int v = (i < NOUT) ? g_cnt[rel][i] : 0;
    int lane = threadIdx.x & 31, wid = threadIdx.x >> 5;
    int inc = v;
    #pragma unroll
    for (int o = 1; o < 32; o <<= 1) {
        int u = __shfl_up_sync(0xffffffffu, inc, o);
        if (lane >= o) inc += u;
    }
    if (lane == 31) ws[wid] = inc;
    __syncthreads();
    if (wid == 0) {
        int x = ws[lane];
        #pragma unroll
        for (int o = 1; o < 32; o <<= 1) {
            int u = __shfl_up_sync(0xffffffffu, x, o);
            if (lane >= o) x += u;
        }
        ws[lane] = x;
    }
    __syncthreads();
    int excl = inc - v + (wid > 0 ? ws[wid - 1] : 0) + g_pbase[rel][blockIdx.x];
    if (i < NOUT) { g_off[rel][i] = excl; g_cur[rel][i] = excl; }
}

// ---------------------------------------------------------------------------
// K4: scatter both relations into CSR (source index only)
// ---------------------------------------------------------------------------
__global__ void k_scatter2(const int* __restrict__ s0, const int* __restrict__ d0,
                           const int* __restrict__ s1, const int* __restrict__ d1) {
    int i = blockIdx.x * 256 + threadIdx.x;
    if (i >= E) return;
    int p0 = atomicAdd(&g_cur[0][d0[i]], 1);
    g_csrc[0][p0] = s0[i];
    int p1 = atomicAdd(&g_cur[1][d1[i]], 1);
    g_csrc[1][p1] = s1[i];
}

// ---------------------------------------------------------------------------
// K5: fused per-destination aggregation (both relations) + semantic attention.
//     One warp per output node; no intermediate g_emb round-trip.
// ---------------------------------------------------------------------------
__global__ __launch_bounds__(256) void k_aggfin(
    const float* __restrict__ rel_l, const float* __restrict__ rel_r,
    float* __restrict__ outp)
{
    int n = blockIdx.x * 8 + (threadIdx.x >> 5);
    if (n >= NOUT) return;
    int lane = threadIdx.x & 31;
    int h  = lane >> 3;
    int c0 = lane * 2;
    int ci = c0 & 15;

    // relation 0 (writes, sources = authors)
    float ewx, ewy;
    {
        const int* csrc = g_csrc[0];
        int beg = g_off[0][n], end = g_off[0][n + 1];
        float s = 0.f, a0 = 0.f, a1 = 0.f;
        #pragma unroll 4
        for (int e = beg; e < end; e++) {
            int srci = csrc[e];
            float wg = g_easrc_w[(size_t)srci * H + h];
            float2 xj = *(const float2*)&g_l_author[(size_t)srci * DOUT + c0];
            s  += wg;
            a0 += wg * xj.x;
            a1 += wg * xj.y;
        }
        float inv = 1.f / (s + 1e-16f);
        ewx = a0 * inv; ewy = a1 * inv;
    }
    // relation 1 (cites, sources = papers)
    float ecx, ecy;
    {
        const int* csrc = g_csrc[1];
        int beg = g_off[1][n], end = g_off[1][n + 1];
        float s = 0.f, a0 = 0.f, a1 = 0.f;
        #pragma unroll 4
        for (int e = beg; e < end; e++) {
            int srci = csrc[e];
            float wg = g_easrc_c[(size_t)srci * H + h];
            float2 xj = *(const float2*)&g_l_paper[(size_t)srci * DOUT + c0];
            s  += wg;
            a0 += wg * xj.x;
            a1 += wg * xj.y;
        }
        float inv = 1.f / (s + 1e-16f);
        ecx = a0 * inv; ecy = a1 * inv;
    }

    float2 es = *(const float2*)&g_l_paper[(size_t)n * DOUT + c0];

    float al = es.x * __ldg(&rel_l[h * C + ci]) + es.y * __ldg(&rel_l[h * C + ci + 1]);
    float r0 = ewx * __ldg(&rel_r[0 * H * C + h * C + ci]) + ewy * __ldg(&rel_r[0 * H * C + h * C + ci + 1]);
    float r1 = ecx * __ldg(&rel_r[1 * H * C + h * C + ci]) + ecy * __ldg(&rel_r[1 * H * C + h * C + ci + 1]);
    float r2 = es.x * __ldg(&rel_r[2 * H * C + h * C + ci]) + es.y * __ldg(&rel_r[2 * H * C + h * C + ci + 1]);

    #pragma unroll
    for (int o = 1; o <= 4; o <<= 1) {
        al += __shfl_xor_sync(0xffffffffu, al, o);
        r0 += __shfl_xor_sync(0xffffffffu, r0, o);
        r1 += __shfl_xor_sync(0xffffffffu, r1, o);
        r2 += __shfl_xor_sync(0xffffffffu, r2, o);
    }

    float x0 = al + r0; x0 = fmaxf(x0, 0.2f * x0);
    float x1 = al + r1; x1 = fmaxf(x1, 0.2f * x1);
    float x2 = al + r2; x2 = fmaxf(x2, 0.2f * x2);
    float mx = fmaxf(x0, fmaxf(x1, x2));
    float e0 = __expf(x0 - mx), e1 = __expf(x1 - mx), e2 = __expf(x2 - mx);
    float ib = 1.f / (e0 + e1 + e2);
    float b0 = e0 * ib, b1 = e1 * ib, b2 = e2 * ib;

    float o0 = fmaxf(ewx * b0 + ecx * b1 + es.x * b2, 0.f);
    float o1 = fmaxf(ewy * b0 + ecy * b1 + es.y * b2, 0.f);
    *(float2*)&outp[(size_t)n * DOUT + c0] = make_float2(o0, o1);
}

// ---------------------------------------------------------------------------
// Launch. Order puts gemm(paper) at slot 4: the ncu capture slot.
// ---------------------------------------------------------------------------
extern "C" void kernel_launch(void* const* d_in, const int* in_sizes, int n_in,
                              void* d_out, int out_size) {
    (void)in_sizes; (void)out_size;
    if (n_in < 16) return;
    const float* x_author   = (const float*)d_in[0];
    const float* x_paper    = (const float*)d_in[1];
    const float* W_l_author = (const float*)d_in[2];
    const float* b_l_author = (const float*)d_in[3];
    const float* W_l_paper  = (const float*)d_in[4];
    const float* b_l_paper  = (const float*)d_in[5];
    // d_in[6], d_in[7] (W_r_paper, b_r_paper): softmax-invariant -> unused
    const float* attn_w     = (const float*)d_in[8];
    const float* attn_c     = (const float*)d_in[9];
    const float* rel_l      = (const float*)d_in[10];
    const float* rel_r      = (const float*)d_in[11];
    const int*   src_w      = (const int*)d_in[12];
    const int*   dst_w      = (const int*)d_in[13];
    const int*   src_c      = (const int*)d_in[14];
    const int*   dst_c      = (const int*)d_in[15];
    float* outp = (float*)d_out;

    k_zero<<<(2 * NOUT + 255) / 256, 256>>>();                                        // 1
    k_hist2<<<(E + 255) / 256, 256>>>(dst_w, dst_c);                                  // 2
    k_gemm_mma<<<(NA + 127) / 128, 256>>>(x_author, NA, W_l_author, b_l_author, attn_w, 0); // 3
    k_gemm_mma<<<(NP + 127) / 128, 256>>>(x_paper,  NP, W_l_paper,  b_l_paper,  attn_c, 1); // 4 <- profiled
    k_scanA<<<dim3(SCB, 2), 1024>>>();                                                // 5
    k_scanB<<<1, 2>>>();                                                              // 6
    k_scanC<<<dim3(SCB, 2), 1024>>>();                                                // 7
    k_scatter2<<<(E + 255) / 256, 256>>>(src_w, dst_w, src_c, dst_c);                 // 8
    k_aggfin<<<(NOUT + 7) / 8, 256>>>(rel_l, rel_r, outp);                            // 9
}

// round 9
// speedup vs baseline: 2.3400x; 1.1429x over previous
#include <cuda_runtime.h>
#include <cuda_bf16.h>
#include <cstdint>

// ---------------------------------------------------------------------------
// Problem constants
// ---------------------------------------------------------------------------
constexpr int H    = 4;
constexpr int C    = 16;
constexpr int DIN  = 128;
constexpr int DOUT = 64;
constexpr int NA   = 150000;
constexpr int NP   = 200000;
constexpr int NOUT = 50000;
constexpr int E    = 1000000;
constexpr int SCB  = (NOUT + 1023) / 1024;   // 49 scan blocks per relation

// ---------------------------------------------------------------------------
// Device scratch (static; no allocations allowed)
// ---------------------------------------------------------------------------
// Features stored bf16 for the edge gathers (halves L2 gather traffic; bf16
// rounding ~2^-9 averaged over segments -> ~1e-4 final rel err, budget 1e-3).
__device__ __align__(16) __nv_bfloat16 g_lb_author[(size_t)NA * DOUT];  // 19.2 MB
__device__ __align__(16) __nv_bfloat16 g_lb_paper [(size_t)NP * DOUT];  // 25.6 MB
// fp32 l_paper kept only for the self-embedding path (first NOUT rows).
__device__ __align__(16) float g_l_paper[(size_t)NOUT * DOUT];          // 12.8 MB
// easrc = exp(alpha_src): logits are O(1) (std ~0.34) so exp never overflows;
// softmax shift-invariance makes the reference's segment-max cancel exactly.
__device__ __align__(16) float g_easrc_w [(size_t)NA * H];
__device__ __align__(16) float g_easrc_c [(size_t)NP * H];
__device__ int g_cnt [2][NOUT];
__device__ int g_off [2][NOUT + 1];
__device__ int g_cur [2][NOUT];
__device__ int g_csrc[2][E];
__device__ int g_part [2][64];
__device__ int g_pbase[2][64];

// fp32 -> (bf16 hi, bf16 lo residual) packed pairs
__device__ __forceinline__ void split2(float a, float b, uint32_t& hi, uint32_t& lo) {
    __nv_bfloat162 h = __floats2bfloat162_rn(a, b);
    float2 hf = __bfloat1622float2(h);
    __nv_bfloat162 l = __floats2bfloat162_rn(a - hf.x, b - hf.y);
    hi = *(uint32_t*)&h;
    lo = *(uint32_t*)&l;
}

__device__ __forceinline__ void mma16816(float* c, uint32_t a0, uint32_t a1, uint32_t a2,
                                         uint32_t a3, uint32_t b0, uint32_t b1) {
    asm volatile(
        "mma.sync.aligned.m16n8k16.row.col.f32.bf16.bf16.f32 "
        "{%0,%1,%2,%3}, {%4,%5,%6,%7}, {%8,%9}, {%0,%1,%2,%3};"
        : "+f"(c[0]), "+f"(c[1]), "+f"(c[2]), "+f"(c[3])
        : "r"(a0), "r"(a1), "r"(a2), "r"(a3), "r"(b0), "r"(b1));
}

// ---------------------------------------------------------------------------
// K1: bf16-split mma.sync GEMM  l = x @ W + b
//     CTA = 128 rows x 64 cols, 128 threads, 4 warps; warp tile 32x64
//     (B-fragments amortized over 32 rows -> ~1.5x less LDS per row).
//     3 passes (hh+hl+lh) -> fp32 acc (err ~2^-16). 4 CTAs/SM target.
//     Epilogue DIRECT from accumulator fragments (no smem staging):
//     stores bf16 l (gather copy), fp32 l for rows < nF, exp(alpha_src).
// ---------------------------------------------------------------------------
constexpr int KCH   = 32;
constexpr int APAD  = 40;            // row stride in halfs (32 + 8 pad) -> conflict-free
constexpr int S_AH  = 0;             // 128*40*2 = 10240
constexpr int S_AL  = 10240;
constexpr int S_WH  = 20480;         // 64*40*2 = 5120
constexpr int S_WL  = 25600;
constexpr int S_BS  = 30720;         // 64 floats bias
constexpr int S_AT  = 30976;         // 64 floats attn (col-indexed)
constexpr int GSMEM = 31232;

__global__ __launch_bounds__(128, 4) void k_gemm_mma(
    const float* __restrict__ A, int N,
    const float* __restrict__ W, const float* __restrict__ bias,
    const float* __restrict__ attn,
    __nv_bfloat16* __restrict__ outB, float* __restrict__ outF, int nF,
    float* __restrict__ alA)
{
    __shared__ __align__(16) char smem[GSMEM];
    __nv_bfloat16* Ah = (__nv_bfloat16*)(smem + S_AH);
    __nv_bfloat16* Al = (__nv_bfloat16*)(smem + S_AL);
    __nv_bfloat16* Wh = (__nv_bfloat16*)(smem + S_WH);
    __nv_bfloat16* Wl = (__nv_bfloat16*)(smem + S_WL);
    float* bs  = (float*)(smem + S_BS);
    float* as_ = (float*)(smem + S_AT);

    const int tid  = threadIdx.x;
    const int lane = tid & 31;
    const int wp   = tid >> 5;           // 4 warps; warp wp owns rows [wp*32, wp*32+32)
    const int g    = lane >> 2;
    const int q    = lane & 3;
    const int row0 = blockIdx.x * 128;

    if (tid < 64) {
        bs[tid]  = bias[tid];
        as_[tid] = attn[(tid >> 4) * (2 * C) + C + (tid & 15)];
    }

    float acc[2][8][4];                  // [row-subtile][nt][frag]
    #pragma unroll
    for (int rt = 0; rt < 2; rt++)
        #pragma unroll
        for (int i = 0; i < 8; i++)
            #pragma unroll
            for (int j = 0; j < 4; j++) acc[rt][i][j] = 0.f;

    for (int c = 0; c < DIN / KCH; c++) {
        const int kc = c * KCH;
        __syncthreads();                 // smem free (first iter: after bias load)
        // A chunk: 128 rows x 32 k (8 float4 per thread, coalesced)
        #pragma unroll
        for (int i = 0; i < 8; i++) {
            int idx = i * 128 + tid;
            int r = idx >> 3, kq = idx & 7;
            int gr = row0 + r;
            float4 f = (gr < N) ? *(const float4*)(A + (size_t)gr * DIN + kc + kq * 4)
                                : make_float4(0.f, 0.f, 0.f, 0.f);
            uint32_t h0, l0, h1, l1;
            split2(f.x, f.y, h0, l0);
            split2(f.z, f.w, h1, l1);
            *(uint2*)(Ah + r * APAD + kq * 4) = make_uint2(h0, h1);
            *(uint2*)(Al + r * APAD + kq * 4) = make_uint2(l0, l1);
        }
        // W chunk transposed: Ws[n][k] = W[kc+k][n]
        #pragma unroll
        for (int i = 0; i < 4; i++) {
            int idx = i * 128 + tid;
            int n = idx >> 3, kq = idx & 7;
            float f0 = W[(kc + kq * 4 + 0) * DOUT + n];
            float f1 = W[(kc + kq * 4 + 1) * DOUT + n];
            float f2 = W[(kc + kq * 4 + 2) * DOUT + n];
            float f3 = W[(kc + kq * 4 + 3) * DOUT + n];
            uint32_t h0, l0, h1, l1;
            split2(f0, f1, h0, l0);
            split2(f2, f3, h1, l1);
            *(uint2*)(Wh + n * APAD + kq * 4) = make_uint2(h0, h1);
            *(uint2*)(Wl + n * APAD + kq * 4) = make_uint2(l0, l1);
        }
        __syncthreads();

        const __nv_bfloat16* Aps[3] = {Ah, Ah, Al};
        const __nv_bfloat16* Bps[3] = {Wh, Wl, Wh};
        #pragma unroll
        for (int p = 0; p < 3; p++) {
            const __nv_bfloat16* Ap = Aps[p];
            const __nv_bfloat16* Bp = Bps[p];
            #pragma unroll
            for (int ks = 0; ks < KCH; ks += 16) {
                uint32_t a[2][4];
                #pragma unroll
                for (int rt = 0; rt < 2; rt++) {
                    int rb = wp * 32 + rt * 16;
                    a[rt][0] = *(const uint32_t*)(Ap + (rb + g)     * APAD + ks + q * 2);
                    a[rt][1] = *(const uint32_t*)(Ap + (rb + g + 8) * APAD + ks + q * 2);
                    a[rt][2] = *(const uint32_t*)(Ap + (rb + g)     * APAD + ks + q * 2 + 8);
                    a[rt][3] = *(const uint32_t*)(Ap + (rb + g + 8) * APAD + ks + q * 2 + 8);
                }
                #pragma unroll
                for (int nt = 0; nt < 8; nt++) {
                    uint32_t b0 = *(const uint32_t*)(Bp + (nt * 8 + g) * APAD + ks + q * 2);
                    uint32_t b1 = *(const uint32_t*)(Bp + (nt * 8 + g) * APAD + ks + q * 2 + 8);
                    mma16816(acc[0][nt], a[0][0], a[0][1], a[0][2], a[0][3], b0, b1);
                    mma16816(acc[1][nt], a[1][0], a[1][1], a[1][2], a[1][3], b0, b1);
                }
            }
        }
    }
    __syncthreads();

    // ---- Epilogue: direct from fragments. Lane owns rows {g, g+8} per rt,
    //      cols {nt*8+q*2, +1}. Head of col = nt>>1 (q*2 < 8). alpha reduced
    //      across the 4 q-lanes sharing a row via shfl.
    #pragma unroll
    for (int rt = 0; rt < 2; rt++) {
        #pragma unroll
        for (int rh = 0; rh < 2; rh++) {
            int row = wp * 32 + rt * 16 + rh * 8 + g;
            int gr  = row0 + row;
            float ph[4] = {0.f, 0.f, 0.f, 0.f};
            #pragma unroll
            for (int nt = 0; nt < 8; nt++) {
                int col = nt * 8 + q * 2;
                float v0 = acc[rt][nt][rh * 2 + 0] + bs[col];
                float v1 = acc[rt][nt][rh * 2 + 1] + bs[col + 1];
                if (gr < N) {
                    *(__nv_bfloat162*)&outB[(size_t)gr * DOUT + col] =
                        __floats2bfloat162_rn(v0, v1);
                    if (gr < nF)
                        *(float2*)&outF[(size_t)gr * DOUT + col] = make_float2(v0, v1);
                }
                ph[nt >> 1] += fmaxf(v0, 0.2f * v0) * as_[col]
                             + fmaxf(v1, 0.2f * v1) * as_[col + 1];
            }
            #pragma unroll
            for (int hh = 0; hh < 4; hh++) {
                ph[hh] += __shfl_xor_sync(0xffffffffu, ph[hh], 1);
                ph[hh] += __shfl_xor_sync(0xffffffffu, ph[hh], 2);
            }
            if (q == 0 && gr < N)
                *(float4*)&alA[(size_t)gr * H] = make_float4(
                    __expf(ph[0]), __expf(ph[1]), __expf(ph[2]), __expf(ph[3]));
        }
    }
}

// ---------------------------------------------------------------------------
// K0: zero edge counters
// ---------------------------------------------------------------------------
__global__ void k_zero() {
    int i = blockIdx.x * 256 + threadIdx.x;
    if (i < 2 * NOUT) (&g_cnt[0][0])[i] = 0;
}

// ---------------------------------------------------------------------------
// K2: histogram both relations in one pass
// ---------------------------------------------------------------------------
__global__ void k_hist2(const int* __restrict__ d0, const int* __restrict__ d1) {
    int i = blockIdx.x * 256 + threadIdx.x;
    if (i >= E) return;
    atomicAdd(&g_cnt[0][d0[i]], 1);
    atomicAdd(&g_cnt[1][d1[i]], 1);
}

// ---------------------------------------------------------------------------
// K3a/b/c: parallel exclusive scan over counts
// ---------------------------------------------------------------------------
__global__ void k_scanA() {                    // grid (SCB, 2), block 1024
    __shared__ int ws[32];
    int rel = blockIdx.y;
    int i = blockIdx.x * 1024 + threadIdx.x;
    int v = (i < NOUT) ? g_cnt[rel][i] : 0;
    int lane = threadIdx.x & 31, wid = threadIdx.x >> 5;
    #pragma unroll
    for (int o = 16; o > 0; o >>= 1) v += __shfl_xor_sync(0xffffffffu, v, o);
    if (lane == 0) ws[wid] = v;
    __syncthreads();
    if (wid == 0) {
        int x = ws[lane];
        #pragma unroll
        for (int o = 16; o > 0; o >>= 1) x += __shfl_xor_sync(0xffffffffu, x, o);
        if (lane == 0) g_part[rel][blockIdx.x] = x;
    }
}
__global__ void k_scanB() {                    // 1 block, 2 threads
    int rel = threadIdx.x;
    if (rel >= 2) return;
    int run = 0;
    for (int b = 0; b < SCB; b++) { g_pbase[rel][b] = run; run += g_part[rel][b]; }
    g_off[rel][NOUT] = run;                    // == E
}
__global__ void k_scanC() {                    // grid (SCB, 2), block 1024
    __shared__ int ws[32];
    int rel = blockIdx.y;
    int i = blockIdx.x * 1024 + threadIdx.x;
    int v = (i < NOUT) ? g_cnt[rel][i] : 0;
    int lane = threadIdx.x & 31, wid = threadIdx.x >> 5;
    int inc = v;
    #pragma unroll
    for (int o = 1; o < 32; o <<= 1) {
        int u = __shfl_up_sync(0xffffffffu, inc, o);
        if (lane >= o) inc += u;
    }
    if (lane == 31) ws[wid] = inc;
    __syncthreads();
    if (wid == 0) {
        int x = ws[lane];
        #pragma unroll
        for (int o = 1; o < 32; o <<= 1) {
            int u = __shfl_up_sync(0xffffffffu, x, o);
            if (lane >= o) x += u;
        }
        ws[lane] = x;
    }
    __syncthreads();
    int excl = inc - v + (wid > 0 ? ws[wid - 1] : 0) + g_pbase[rel][blockIdx.x];
    if (i < NOUT) { g_off[rel][i] = excl; g_cur[rel][i] = excl; }
}

// ---------------------------------------------------------------------------
// K4: scatter both relations into CSR (source index only)
// ---------------------------------------------------------------------------
__global__ void k_scatter2(const int* __restrict__ s0, const int* __restrict__ d0,
                           const int* __restrict__ s1, const int* __restrict__ d1) {
    int i = blockIdx.x * 256 + threadIdx.x;
    if (i >= E) return;
    int p0 = atomicAdd(&g_cur[0][d0[i]], 1);
    g_csrc[0][p0] = s0[i];
    int p1 = atomicAdd(&g_cur[1][d1[i]], 1);
    g_csrc[1][p1] = s1[i];
}

// ---------------------------------------------------------------------------
// K5: fused aggregation (both relations, bf16 feature gathers) + semantic
//     attention. One warp per output node.
// ---------------------------------------------------------------------------
__global__ __launch_bounds__(256) void k_aggfin(
    const float* __restrict__ rel_l, const float* __restrict__ rel_r,
    float* __restrict__ outp)
{
    int n = blockIdx.x * 8 + (threadIdx.x >> 5);
    if (n >= NOUT) return;
    int lane = threadIdx.x & 31;
    int h  = lane >> 3;
    int c0 = lane * 2;
    int ci = c0 & 15;

    // relation 0 (writes, sources = authors)
    float ewx, ewy;
    {
        const int* csrc = g_csrc[0];
        int beg = g_off[0][n], end = g_off[0][n + 1];
        float s = 0.f, a0 = 0.f, a1 = 0.f;
        #pragma unroll 4
        for (int e = beg; e < end; e++) {
            int srci = csrc[e];
            float wg = g_easrc_w[(size_t)srci * H + h];
            float2 xj = __bfloat1622float2(
                *(const __nv_bfloat162*)&g_lb_author[(size_t)srci * DOUT + c0]);
            s  += wg;
            a0 += wg * xj.x;
            a1 += wg * xj.y;
        }
        float inv = 1.f / (s + 1e-16f);
        ewx = a0 * inv; ewy = a1 * inv;
    }
    // relation 1 (cites, sources = papers)
    float ecx, ecy;
    {
        const int* csrc = g_csrc[1];
        int beg = g_off[1][n], end = g_off[1][n + 1];
        float s = 0.f, a0 = 0.f, a1 = 0.f;
        #pragma unroll 4
        for (int e = beg; e < end; e++) {
            int srci = csrc[e];
            float wg = g_easrc_c[(size_t)srci * H + h];
            float2 xj = __bfloat1622float2(
                *(const __nv_bfloat162*)&g_lb_paper[(size_t)srci * DOUT + c0]);
            s  += wg;
            a0 += wg * xj.x;
            a1 += wg * xj.y;
        }
        float inv = 1.f / (s + 1e-16f);
        ecx = a0 * inv; ecy = a1 * inv;
    }

    float2 es = *(const float2*)&g_l_paper[(size_t)n * DOUT + c0];   // fp32 self

    float al = es.x * __ldg(&rel_l[h * C + ci]) + es.y * __ldg(&rel_l[h * C + ci + 1]);
    float r0 = ewx * __ldg(&rel_r[0 * H * C + h * C + ci]) + ewy * __ldg(&rel_r[0 * H * C + h * C + ci + 1]);
    float r1 = ecx * __ldg(&rel_r[1 * H * C + h * C + ci]) + ecy * __ldg(&rel_r[1 * H * C + h * C + ci + 1]);
    float r2 = es.x * __ldg(&rel_r[2 * H * C + h * C + ci]) + es.y * __ldg(&rel_r[2 * H * C + h * C + ci + 1]);

    #pragma unroll
    for (int o = 1; o <= 4; o <<= 1) {
        al += __shfl_xor_sync(0xffffffffu, al, o);
        r0 += __shfl_xor_sync(0xffffffffu, r0, o);
        r1 += __shfl_xor_sync(0xffffffffu, r1, o);
        r2 += __shfl_xor_sync(0xffffffffu, r2, o);
    }

    float x0 = al + r0; x0 = fmaxf(x0, 0.2f * x0);
    float x1 = al + r1; x1 = fmaxf(x1, 0.2f * x1);
    float x2 = al + r2; x2 = fmaxf(x2, 0.2f * x2);
    float mx = fmaxf(x0, fmaxf(x1, x2));
    float e0 = __expf(x0 - mx), e1 = __expf(x1 - mx), e2 = __expf(x2 - mx);
    float ib = 1.f / (e0 + e1 + e2);
    float b0 = e0 * ib, b1 = e1 * ib, b2 = e2 * ib;

    float o0 = fmaxf(ewx * b0 + ecx * b1 + es.x * b2, 0.f);
    float o1 = fmaxf(ewy * b0 + ecy * b1 + es.y * b2, 0.f);
    *(float2*)&outp[(size_t)n * DOUT + c0] = make_float2(o0, o1);
}

// ---------------------------------------------------------------------------
// Launch. Slot 4 = gemm(paper): the ncu capture slot.
// ---------------------------------------------------------------------------
extern "C" void kernel_launch(void* const* d_in, const int* in_sizes, int n_in,
                              void* d_out, int out_size) {
    (void)in_sizes; (void)out_size;
    if (n_in < 16) return;
    const float* x_author   = (const float*)d_in[0];
    const float* x_paper    = (const float*)d_in[1];
    const float* W_l_author = (const float*)d_in[2];
    const float* b_l_author = (const float*)d_in[3];
    const float* W_l_paper  = (const float*)d_in[4];
    const float* b_l_paper  = (const float*)d_in[5];
    // d_in[6], d_in[7] (W_r_paper, b_r_paper): softmax-invariant -> unused
    const float* attn_w     = (const float*)d_in[8];
    const float* attn_c     = (const float*)d_in[9];
    const float* rel_l      = (const float*)d_in[10];
    const float* rel_r      = (const float*)d_in[11];
    const int*   src_w      = (const int*)d_in[12];
    const int*   dst_w      = (const int*)d_in[13];
    const int*   src_c      = (const int*)d_in[14];
    const int*   dst_c      = (const int*)d_in[15];
    float* outp = (float*)d_out;

    __nv_bfloat16* lbA; cudaGetSymbolAddress((void**)&lbA, g_lb_author);
    __nv_bfloat16* lbP; cudaGetSymbolAddress((void**)&lbP, g_lb_paper);
    float* lP;  cudaGetSymbolAddress((void**)&lP,  g_l_paper);
    float* eaW; cudaGetSymbolAddress((void**)&eaW, g_easrc_w);
    float* eaC; cudaGetSymbolAddress((void**)&eaC, g_easrc_c);

    k_zero<<<(2 * NOUT + 255) / 256, 256>>>();                                        // 1
    k_hist2<<<(E + 255) / 256, 256>>>(dst_w, dst_c);                                  // 2
    k_gemm_mma<<<(NA + 127) / 128, 128>>>(x_author, NA, W_l_author, b_l_author,
                                          attn_w, lbA, lP, 0, eaW);                   // 3
    k_gemm_mma<<<(NP + 127) / 128, 128>>>(x_paper,  NP, W_l_paper,  b_l_paper,
                                          attn_c, lbP, lP, NOUT, eaC);                // 4 <- profiled
    k_scanA<<<dim3(SCB, 2), 1024>>>();                                                // 5
    k_scanB<<<1, 2>>>();                                                              // 6
    k_scanC<<<dim3(SCB, 2), 1024>>>();                                                // 7
    k_scatter2<<<(E + 255) / 256, 256>>>(src_w, dst_w, src_c, dst_c);                 // 8
    k_aggfin<<<(NOUT + 7) / 8, 256>>>(rel_l, rel_r, outp);                            // 9
}